// round 11
// baseline (speedup 1.0000x reference)
#include <cuda_runtime.h>
#include <math_constants.h>
#include <cstdint>

// SubsetOperator soft k-hot (K=16, TAU=1), exp-domain, fixed shift (-10):
//   e = exp(s0-10); repeat K: p = e/Z; khot += p; e *= (1-p)
// 3-iteration bodies from 4 moments of the entry state t:
//   A=sum t, B=sum t^2, C=sum t^3, D=sum t^4
//   p0=1/A; Z1=A-B*p0; p1=1/Z1; S21=B-2C*p0+D*p0^2; Z2=Z1-S21*p1; p2=1/Z2
// State renormalized at body end (t <- t3*p2) so folds are u32-fixed-point safe
// (scale 2^28) and reduced with redux.sync.add.u32 at both levels.
// 6 chains/row (was 8). Wave-2 CTAs nanosleep once to de-phase from wave-1.

#define ROWS 4096
#define NCOL 8192
#define THREADS 512
#define PAIRS 8
#define GRID 296

typedef unsigned long long u64;
typedef unsigned int u32;

#define MUL2(d,a,b)    asm("mul.rn.f32x2 %0, %1, %2;"     : "=l"(d) : "l"(a), "l"(b))
#define ADD2(d,a,b)    asm("add.rn.f32x2 %0, %1, %2;"     : "=l"(d) : "l"(a), "l"(b))
#define FMA2(d,a,b,c)  asm("fma.rn.f32x2 %0, %1, %2, %3;" : "=l"(d) : "l"(a), "l"(b), "l"(c))
#define PACK2(d,lo,hi)   asm("mov.b64 %0, {%1, %2};" : "=l"(d) : "f"(lo), "f"(hi))
#define UNPACK2(lo,hi,s) asm("mov.b64 {%0, %1}, %2;" : "=f"(lo), "=f"(hi) : "l"(s))

__device__ __forceinline__ float rcp_fast(float x) {
    float r; asm("rcp.approx.f32 %0, %1;" : "=f"(r) : "f"(x)); return r;
}
__device__ __forceinline__ float ex2_fast(float x) {
    float r; asm("ex2.approx.f32 %0, %1;" : "=f"(r) : "f"(x)); return r;
}
__device__ __forceinline__ u32 f2u_rni(float x) {
    u32 u; asm("cvt.rni.u32.f32 %0, %1;" : "=r"(u) : "f"(x)); return u;
}
__device__ __forceinline__ float u2f(u32 u) {
    float x; asm("cvt.rn.f32.u32 %0, %1;" : "=f"(x) : "r"(u)); return x;
}
__device__ __forceinline__ u32 redux_add_u32(u32 v) {
    u32 d; asm("redux.sync.add.u32 %0, %1, 0xffffffff;" : "=r"(d) : "r"(v)); return d;
}

#define SCALE_F 268435456.0f            // 2^28
#define ISCALE_F 3.725290298461914e-9f  // 2^-28

__device__ __forceinline__ void cp16(u32 dst, const void* src) {
    asm volatile("cp.async.cg.shared.global [%0], [%1], 16;" :: "r"(dst), "l"(src));
}

__device__ __forceinline__ void prefetch_row(const float* s, const float* gg,
                                             int row, float* tile, int tid, bool valid) {
    if (valid) {
        const float4* s4 = (const float4*)(s + (size_t)row * NCOL);
        const float4* g4 = (const float4*)(gg + (size_t)row * NCOL);
        u32 ds = (u32)__cvta_generic_to_shared(tile);
#pragma unroll
        for (int c = 0; c < 4; c++) {
            cp16(ds + (u32)(tid + c * THREADS) * 16u,                  s4 + tid + c * THREADS);
            cp16(ds + (u32)NCOL * 4u + (u32)(tid + c * THREADS) * 16u, g4 + tid + c * THREADS);
        }
    }
    asm volatile("cp.async.commit_group;");
}

__global__ void __launch_bounds__(THREADS, 2)
subset_op_kernel(const float* __restrict__ scores,
                 const float* __restrict__ g,
                 float* __restrict__ out) {
    extern __shared__ __align__(16) float tile[];     // 64 KB
    __shared__ __align__(16) uint4  redq[2][16];
    __shared__ __align__(16) float4 redp[16];

    const int tid  = threadIdx.x;
    const int lane = tid & 31;
    const int wid  = tid >> 5;
    const float L2E = 1.4426950408889634f;
    const float CC  = -10.0f * L2E;

    int row = blockIdx.x;
    prefetch_row(scores, g, row, tile, tid, true);
    if (blockIdx.x >= 148) __nanosleep(700);          // de-phase wave-2 CTA

    for (; row < ROWS; row += GRID) {
        asm volatile("cp.async.wait_group 0;");
        __syncthreads();

        // ---- prologue: exp + f32 4-moment partials of raw e ----
        u64 t[PAIRS], nk[PAIRS];
        const float4* ts4 = (const float4*)tile;
        const float4* tg4 = (const float4*)(tile + NCOL);
        u64 ma = 0ull, mb = 0ull, mc = 0ull, md = 0ull;
#pragma unroll
        for (int c = 0; c < 4; c++) {
            const int i4 = tid + c * THREADS;
            float4 a = ts4[i4];
            float4 b = tg4[i4];
            float e0 = ex2_fast(fmaf(a.x + b.x, L2E, CC));
            float e1 = ex2_fast(fmaf(a.y + b.y, L2E, CC));
            float e2 = ex2_fast(fmaf(a.z + b.z, L2E, CC));
            float e3 = ex2_fast(fmaf(a.w + b.w, L2E, CC));
            PACK2(t[2 * c],     e0, e1);
            PACK2(t[2 * c + 1], e2, e3);
            nk[2 * c] = 0ull; nk[2 * c + 1] = 0ull;
#pragma unroll
            for (int h = 0; h < 2; h++) {
                u64 tv = t[2 * c + h], sq;
                MUL2(sq, tv, tv);
                ADD2(ma, ma, tv);
                ADD2(mb, mb, sq);
                FMA2(mc, sq, tv, mc);
                FMA2(md, sq, sq, md);
            }
        }
        prefetch_row(scores, g, row + GRID, tile, tid, (row + GRID) < ROWS);

        // f32 two-level reduction of (A,B) and (C,D) packed
        float Af, Bf, Cf, Df;
        {
            float lo, hi;
            UNPACK2(lo, hi, ma); Af = lo + hi;
            UNPACK2(lo, hi, mb); Bf = lo + hi;
            UNPACK2(lo, hi, mc); Cf = lo + hi;
            UNPACK2(lo, hi, md); Df = lo + hi;
            u64 u, w;
            PACK2(u, Af, Bf);
            PACK2(w, Cf, Df);
#pragma unroll
            for (int o = 16; o > 0; o >>= 1) {
                u64 x = __shfl_xor_sync(0xffffffffu, u, o);
                u64 y = __shfl_xor_sync(0xffffffffu, w, o);
                ADD2(u, u, x);
                ADD2(w, w, y);
            }
            if (lane == 0) {
                float4 q;
                UNPACK2(q.x, q.y, u);
                UNPACK2(q.z, q.w, w);
                redp[wid] = q;
            }
            __syncthreads();
            float4 v = redp[lane & 15];
            PACK2(u, v.x, v.y);
            PACK2(w, v.z, v.w);
#pragma unroll
            for (int o = 8; o > 0; o >>= 1) {
                u64 x = __shfl_xor_sync(0xffffffffu, u, o);
                u64 y = __shfl_xor_sync(0xffffffffu, w, o);
                ADD2(u, u, x);
                ADD2(w, w, y);
            }
            UNPACK2(Af, Bf, u);
            UNPACK2(Cf, Df, w);
        }

        // ---- 5 bodies x 3 iterations + final iteration ----
#pragma unroll
        for (int r = 0; r < 5; r++) {
            // scalars from entry moments (exact 2-step lookahead)
            float p0 = rcp_fast(Af);
            float Z1 = fmaf(-Bf, p0, Af);
            float p1 = rcp_fast(Z1);
            float x  = fmaf(Df, p0, -(Cf + Cf));   // D*p0 - 2C
            float S21 = fmaf(x, p0, Bf);           // B - 2C*p0 + D*p0^2
            float Z2 = fmaf(-S21, p1, Z1);
            float p2 = rcp_fast(Z2);
            u64 n0, n1, n2, pv2;
            PACK2(n0, -p0, -p0);
            PACK2(n1, -p1, -p1);
            PACK2(n2, -p2, -p2);
            PACK2(pv2, p2, p2);

            // iterations A, B
#pragma unroll
            for (int j = 0; j < PAIRS; j++) {
                u64 q;
                MUL2(q, t[j], n0);
                ADD2(nk[j], nk[j], q);
                FMA2(t[j], q, t[j], t[j]);
            }
#pragma unroll
            for (int j = 0; j < PAIRS; j++) {
                u64 q;
                MUL2(q, t[j], n1);
                ADD2(nk[j], nk[j], q);
                FMA2(t[j], q, t[j], t[j]);
            }

            if (r < 4) {
                // iteration C + renorm + fold 4 moments of new t
                u64 fa = 0ull, fb = 0ull, fc = 0ull, fd = 0ull;
#pragma unroll
                for (int j = 0; j < PAIRS; j++) {
                    u64 q, tn, sq;
                    MUL2(q, t[j], n2);
                    ADD2(nk[j], nk[j], q);
                    FMA2(tn, q, t[j], t[j]);
                    MUL2(t[j], tn, pv2);          // renormalized state
                    MUL2(sq, t[j], t[j]);
                    ADD2(fa, fa, t[j]);
                    ADD2(fb, fb, sq);
                    FMA2(fc, sq, t[j], fc);
                    FMA2(fd, sq, sq, fd);
                }
                float lo, hi, pa, pb, pc, pd;
                UNPACK2(lo, hi, fa); pa = lo + hi;
                UNPACK2(lo, hi, fb); pb = lo + hi;
                UNPACK2(lo, hi, fc); pc = lo + hi;
                UNPACK2(lo, hi, fd); pd = lo + hi;
                u32 ua = redux_add_u32(f2u_rni(pa * SCALE_F));
                u32 ub = redux_add_u32(f2u_rni(pb * SCALE_F));
                u32 uc = redux_add_u32(f2u_rni(pc * SCALE_F));
                u32 ud = redux_add_u32(f2u_rni(pd * SCALE_F));
                if (lane == 0) {
                    uint4 q; q.x = ua; q.y = ub; q.z = uc; q.w = ud;
                    redq[r & 1][wid] = q;
                }
                __syncthreads();
                uint4 v = redq[r & 1][lane & 15];
                u32 xa = (lane < 16) ? v.x : 0u;
                u32 xb = (lane < 16) ? v.y : 0u;
                u32 xc = (lane < 16) ? v.z : 0u;
                u32 xd = (lane < 16) ? v.w : 0u;
                Af = u2f(redux_add_u32(xa)) * ISCALE_F;
                Bf = u2f(redux_add_u32(xb)) * ISCALE_F;
                Cf = u2f(redux_add_u32(xc)) * ISCALE_F;
                Df = u2f(redux_add_u32(xd)) * ISCALE_F;
            } else {
                // body 4: iteration C + renorm + fold A only
                u64 fa = 0ull;
#pragma unroll
                for (int j = 0; j < PAIRS; j++) {
                    u64 q, tn;
                    MUL2(q, t[j], n2);
                    ADD2(nk[j], nk[j], q);
                    FMA2(tn, q, t[j], t[j]);
                    MUL2(t[j], tn, pv2);
                    ADD2(fa, fa, t[j]);
                }
                float lo, hi;
                UNPACK2(lo, hi, fa);
                u32 ua = redux_add_u32(f2u_rni((lo + hi) * SCALE_F));
                if (lane == 0) {
                    uint4 q; q.x = ua; q.y = 0u; q.z = 0u; q.w = 0u;
                    redq[0][wid] = q;
                }
                __syncthreads();
                uint4 v = redq[0][lane & 15];
                u32 xa = (lane < 16) ? v.x : 0u;
                Af = u2f(redux_add_u32(xa)) * ISCALE_F;
            }
        }

        // ---- iteration 16: khot accumulate only ----
        {
            float p = rcp_fast(Af);
            u64 nv; PACK2(nv, -p, -p);
#pragma unroll
            for (int j = 0; j < PAIRS; j++) {
                u64 q;
                MUL2(q, t[j], nv);
                ADD2(nk[j], nk[j], q);
            }
        }

        // ---- store khot = -nk ----
        float4* o4 = (float4*)(out + (size_t)row * NCOL);
#pragma unroll
        for (int c = 0; c < 4; c++) {
            float a0, a1, a2, a3;
            UNPACK2(a0, a1, nk[2 * c]);
            UNPACK2(a2, a3, nk[2 * c + 1]);
            float4 v; v.x = -a0; v.y = -a1; v.z = -a2; v.w = -a3;
            o4[tid + c * THREADS] = v;
        }
    }
}

extern "C" void kernel_launch(void* const* d_in, const int* in_sizes, int n_in,
                              void* d_out, int out_size) {
    const float* scores = (const float*)d_in[0];
    const float* g      = (const float*)d_in[1];
    float* out          = (float*)d_out;
    cudaFuncSetAttribute(subset_op_kernel,
                         cudaFuncAttributeMaxDynamicSharedMemorySize, 2 * NCOL * 4);
    subset_op_kernel<<<GRID, THREADS, 2 * NCOL * 4>>>(scores, g, out);
}

// round 12
// speedup vs baseline: 1.1220x; 1.1220x over previous
#include <cuda_runtime.h>
#include <math_constants.h>
#include <cstdint>

// SubsetOperator soft k-hot (K=16, TAU=1), exp-domain, fixed shift (-10):
//   e = exp(s0-10); repeat K: p = e/Z; khot += p; e *= (1-p)
// 2-iter bodies with FREE renormalization via the sign-flip identity:
//   b = -p1*t  =>  b*b + b = -( p1*t*(1-p1*t) ) = -(renormalized next state)
// State is stored NEGATED after every body; the sign is absorbed into the
// per-body scalar constants (compile-time, loop unrolled) and the fold scale.
// Folds: per-warp redux.sync.add.u32 -> lane0 atomicAdd into pre-zeroed u32
// accumulators; post-barrier = one LDS.64 + cvt + rcp chain.

#define ROWS 4096
#define NCOL 8192
#define THREADS 512
#define PAIRS 8
#define GRID 296

typedef unsigned long long u64;
typedef unsigned int u32;

#define MUL2(d,a,b)    asm("mul.rn.f32x2 %0, %1, %2;"     : "=l"(d) : "l"(a), "l"(b))
#define ADD2(d,a,b)    asm("add.rn.f32x2 %0, %1, %2;"     : "=l"(d) : "l"(a), "l"(b))
#define FMA2(d,a,b,c)  asm("fma.rn.f32x2 %0, %1, %2, %3;" : "=l"(d) : "l"(a), "l"(b), "l"(c))
#define PACK2(d,lo,hi)   asm("mov.b64 %0, {%1, %2};" : "=l"(d) : "f"(lo), "f"(hi))
#define UNPACK2(lo,hi,s) asm("mov.b64 {%0, %1}, %2;" : "=f"(lo), "=f"(hi) : "l"(s))

__device__ __forceinline__ float rcp_fast(float x) {
    float r; asm("rcp.approx.f32 %0, %1;" : "=f"(r) : "f"(x)); return r;
}
__device__ __forceinline__ float ex2_fast(float x) {
    float r; asm("ex2.approx.f32 %0, %1;" : "=f"(r) : "f"(x)); return r;
}
__device__ __forceinline__ u32 f2u_rni(float x) {
    u32 u; asm("cvt.rni.u32.f32 %0, %1;" : "=r"(u) : "f"(x)); return u;
}
__device__ __forceinline__ float u2f(u32 u) {
    float x; asm("cvt.rn.f32.u32 %0, %1;" : "=f"(x) : "r"(u)); return x;
}
__device__ __forceinline__ u32 redux_add_u32(u32 v) {
    u32 d; asm("redux.sync.add.u32 %0, %1, 0xffffffff;" : "=r"(d) : "r"(v)); return d;
}

#define SCALE_F  268435456.0f            // 2^28
#define NSCALE_F -268435456.0f           // -2^28 (fold of negated state)
#define ISCALE_F 3.725290298461914e-9f   // 2^-28

__device__ __forceinline__ void cp16(u32 dst, const void* src) {
    asm volatile("cp.async.cg.shared.global [%0], [%1], 16;" :: "r"(dst), "l"(src));
}

__device__ __forceinline__ void prefetch_row(const float* s, const float* gg,
                                             int row, float* tile, int tid, bool valid) {
    if (valid) {
        const float4* s4 = (const float4*)(s + (size_t)row * NCOL);
        const float4* g4 = (const float4*)(gg + (size_t)row * NCOL);
        u32 ds = (u32)__cvta_generic_to_shared(tile);
#pragma unroll
        for (int c = 0; c < 4; c++) {
            cp16(ds + (u32)(tid + c * THREADS) * 16u,                  s4 + tid + c * THREADS);
            cp16(ds + (u32)NCOL * 4u + (u32)(tid + c * THREADS) * 16u, g4 + tid + c * THREADS);
        }
    }
    asm volatile("cp.async.commit_group;");
}

__global__ void __launch_bounds__(THREADS, 2)
subset_op_kernel(const float* __restrict__ scores,
                 const float* __restrict__ g,
                 float* __restrict__ out) {
    extern __shared__ __align__(16) float tile[];     // 64 KB
    __shared__ __align__(16) float2 redf[16];
    __shared__ __align__(8)  u32 acc[7][2];           // per-body fold accumulators

    const int tid  = threadIdx.x;
    const int lane = tid & 31;
    const int wid  = tid >> 5;
    const float L2E = 1.4426950408889634f;
    const float CC  = -10.0f * L2E;

    int row = blockIdx.x;
    prefetch_row(scores, g, row, tile, tid, true);

    for (; row < ROWS; row += GRID) {
        asm volatile("cp.async.wait_group 0;");
        __syncthreads();
        if (tid < 14) ((u32*)acc)[tid] = 0u;          // zero fold accumulators

        // ---- prologue: exp; (A,B) = (sum t, sum t^2) partials, sigma=+1 ----
        u64 t[PAIRS], nk[PAIRS];
        const float4* ts4 = (const float4*)tile;
        const float4* tg4 = (const float4*)(tile + NCOL);
        u64 ma = 0ull, mb = 0ull;
#pragma unroll
        for (int c = 0; c < 4; c++) {
            const int i4 = tid + c * THREADS;
            float4 a = ts4[i4];
            float4 b = tg4[i4];
            float e0 = ex2_fast(fmaf(a.x + b.x, L2E, CC));
            float e1 = ex2_fast(fmaf(a.y + b.y, L2E, CC));
            float e2 = ex2_fast(fmaf(a.z + b.z, L2E, CC));
            float e3 = ex2_fast(fmaf(a.w + b.w, L2E, CC));
            PACK2(t[2 * c],     e0, e1);
            PACK2(t[2 * c + 1], e2, e3);
            nk[2 * c] = 0ull; nk[2 * c + 1] = 0ull;
            ADD2(ma, ma, t[2 * c]);
            ADD2(ma, ma, t[2 * c + 1]);
            FMA2(mb, t[2 * c],     t[2 * c],     mb);
            FMA2(mb, t[2 * c + 1], t[2 * c + 1], mb);
        }
        prefetch_row(scores, g, row + GRID, tile, tid, (row + GRID) < ROWS);

        // f32 two-level (A,B) reduction, packed
        float Af, Bf;
        {
            float lo, hi;
            UNPACK2(lo, hi, ma); Af = lo + hi;
            UNPACK2(lo, hi, mb); Bf = lo + hi;
            u64 u; PACK2(u, Af, Bf);
#pragma unroll
            for (int o = 16; o > 0; o >>= 1) {
                u64 x = __shfl_xor_sync(0xffffffffu, u, o);
                ADD2(u, u, x);
            }
            if (lane == 0) {
                float2 q; UNPACK2(q.x, q.y, u); redf[wid] = q;
            }
            __syncthreads();
            float2 v = redf[lane & 15];
            PACK2(u, v.x, v.y);
#pragma unroll
            for (int o = 8; o > 0; o >>= 1) {
                u64 x = __shfl_xor_sync(0xffffffffu, u, o);
                ADD2(u, u, x);
            }
            UNPACK2(Af, Bf, u);
        }

        // ---- bodies 0..6: 2 iters + fold; state negated after each body ----
#pragma unroll
        for (int r = 0; r < 7; r++) {
            float p0 = rcp_fast(Af);
            float Z1 = fmaf(-Bf, p0, Af);
            float p1 = rcp_fast(Z1);
            // sigma = +1 for body 0, -1 afterwards: v = -sigma*p
            const float sg = (r == 0) ? -1.0f : 1.0f;
            u64 vv, ww;
            PACK2(vv, sg * p0, sg * p0);
            PACK2(ww, sg * p1, sg * p1);

            // iterA: q = -p0*t_true ; nk += q ; t_st *= (1+q)
#pragma unroll
            for (int j = 0; j < PAIRS; j++) {
                u64 q;
                MUL2(q, t[j], vv);
                ADD2(nk[j], nk[j], q);
                FMA2(t[j], q, t[j], t[j]);
            }
            // iterB: b = -p1*t_true ; nk += b ; t_st = b*b + b  (= -renorm state)
            u64 fa = 0ull, fb = 0ull;
#pragma unroll
            for (int j = 0; j < PAIRS; j++) {
                u64 b;
                MUL2(b, t[j], ww);
                ADD2(nk[j], nk[j], b);
                FMA2(t[j], b, b, b);
                ADD2(fa, fa, t[j]);            // sum of negated state
                FMA2(fb, t[j], t[j], fb);      // sum of squares
            }
            // fold: convert, warp redux, one atomic per warp
            {
                float lo, hi, pa, pb;
                UNPACK2(lo, hi, fa); pa = lo + hi;   // negative
                UNPACK2(lo, hi, fb); pb = lo + hi;
                u32 ua = redux_add_u32(f2u_rni(pa * NSCALE_F));
                u32 ub = redux_add_u32(f2u_rni(pb * SCALE_F));
                if (lane == 0) {
                    atomicAdd(&acc[r][0], ua);
                    atomicAdd(&acc[r][1], ub);
                }
            }
            __syncthreads();
            Af = u2f(acc[r][0]) * ISCALE_F;
            Bf = u2f(acc[r][1]) * ISCALE_F;
        }

        // ---- body 7: iterA + final iteration (no fold, no barrier) ----
        {
            float p0 = rcp_fast(Af);
            float Z1 = fmaf(-Bf, p0, Af);
            float p1 = rcp_fast(Z1);
            u64 vv, ww;                        // sigma = -1
            PACK2(vv, p0, p0);
            PACK2(ww, p1, p1);
#pragma unroll
            for (int j = 0; j < PAIRS; j++) {
                u64 q;
                MUL2(q, t[j], vv);
                ADD2(nk[j], nk[j], q);
                FMA2(t[j], q, t[j], t[j]);
            }
#pragma unroll
            for (int j = 0; j < PAIRS; j++) {
                u64 q;
                MUL2(q, t[j], ww);
                ADD2(nk[j], nk[j], q);
            }
        }

        // ---- store khot = -nk ----
        float4* o4 = (float4*)(out + (size_t)row * NCOL);
#pragma unroll
        for (int c = 0; c < 4; c++) {
            float a0, a1, a2, a3;
            UNPACK2(a0, a1, nk[2 * c]);
            UNPACK2(a2, a3, nk[2 * c + 1]);
            float4 v; v.x = -a0; v.y = -a1; v.z = -a2; v.w = -a3;
            o4[tid + c * THREADS] = v;
        }
        __syncthreads();   // protect redf/acc reuse next row
    }
}

extern "C" void kernel_launch(void* const* d_in, const int* in_sizes, int n_in,
                              void* d_out, int out_size) {
    const float* scores = (const float*)d_in[0];
    const float* g      = (const float*)d_in[1];
    float* out          = (float*)d_out;
    cudaFuncSetAttribute(subset_op_kernel,
                         cudaFuncAttributeMaxDynamicSharedMemorySize, 2 * NCOL * 4);
    subset_op_kernel<<<GRID, THREADS, 2 * NCOL * 4>>>(scores, g, out);
}